// round 7
// baseline (speedup 1.0000x reference)
#include <cuda_runtime.h>
#include <cuda_bf16.h>

// Problem: ToRGBLayer  (B=16, CIN=128, COUT=3, WDIM=512, H=W=256)
// out[b,o,h,w] = sum_i x[b,i,h,w] * style[b,i] * weight[o,i] + bias[o]
// style[b,i]   = dot(w[b,:], affine_w[i,:]) + affine_b[i]
//
// R7: SINGLE fused kernel. Grid = 1024 CTAs @ launch_bounds(256,8) -> whole
// grid resident in wave 1 (needs 128 of 148 SMs), so a grid-wide flag
// barrier is deadlock-free. Blocks 0..255 compute 8 coeffs each (warp-per-
// (b,i)), fence, count into g_done; everyone spins to 256, then runs the
// proven streaming loop (unroll 4, __ldcs/__stcg, 32-reg budget).
// Counters are reset by the last barrier-passer so graph replays are clean.

#define B_    16
#define CIN_  128
#define COUT_ 3
#define WDIM_ 512
#define HW_   65536            // 256*256
#define HW4_  16384            // HW/4 float4 positions
#define NBLK_ 1024             // total CTAs (64 x 16)
#define NPROD_ 256             // producer CTAs (8 coeff-warps each)

__device__ float4 g_coeff[B_ * CIN_];          // {s*w0, s*w1, s*w2, 0}
__device__ volatile unsigned g_done = 0;       // producer completion count
__device__ unsigned g_pass = 0;                // barrier-passer count (reset)

__global__ void __launch_bounds__(256, 8) fused_torgb_kernel(
    const float4* __restrict__ x,         // [B, CIN, HW4_] as float4
    const float4* __restrict__ w,         // [B, WDIM/4]
    const float*  __restrict__ weight,    // [COUT, CIN]
    const float*  __restrict__ bias,      // [COUT]
    const float4* __restrict__ affine_w,  // [CIN, WDIM/4]
    const float*  __restrict__ affine_b,  // [CIN]
    float4*       __restrict__ out)       // [B, COUT, HW4_] as float4
{
    __shared__ float4 sc[CIN_];

    const int tid = threadIdx.x;
    const int bid = blockIdx.y * 64 + blockIdx.x;   // flat block id, gridDim.x==64

    // ---- producer phase: blocks 0..255 compute 8 coeffs each -------------
    if (bid < NPROD_) {
        const int lane = tid & 31;
        const int gw   = (bid << 3) + (tid >> 5);   // global (b,i) pair id
        const int b    = gw >> 7;
        const int i    = gw & (CIN_ - 1);

        const float4* wb = w + b * (WDIM_ / 4);
        const float4* aw = affine_w + i * (WDIM_ / 4);

        float acc = 0.f;
        #pragma unroll
        for (int k = 0; k < 4; k++) {
            float4 a = wb[lane + 32 * k];
            float4 c = aw[lane + 32 * k];
            acc += a.x * c.x + a.y * c.y + a.z * c.z + a.w * c.w;
        }
        #pragma unroll
        for (int off = 16; off > 0; off >>= 1)
            acc += __shfl_down_sync(0xffffffffu, acc, off);

        if (lane == 0) {
            float style = acc + affine_b[i];
            float4 c;
            c.x = style * weight[0 * CIN_ + i];
            c.y = style * weight[1 * CIN_ + i];
            c.z = style * weight[2 * CIN_ + i];
            c.w = 0.f;
            g_coeff[b * CIN_ + i] = c;
            __threadfence();                 // release: coeff visible device-wide
        }
        __syncthreads();
        if (tid == 0) atomicAdd((unsigned*)&g_done, 1u);
    }

    // ---- grid-wide flag barrier (safe: entire grid resident, wave 1) -----
    if (tid == 0) {
        while (g_done < NPROD_) __nanosleep(64);
        __threadfence();                     // acquire
    }
    __syncthreads();

    // ---- stage coefficients ----------------------------------------------
    const int b = blockIdx.y;
    if (tid < CIN_) sc[tid] = g_coeff[b * CIN_ + tid];
    __syncthreads();

    // ---- replay-safe counter reset (1024th passer resets both) -----------
    if (tid == 0) {
        unsigned p = atomicAdd(&g_pass, 1u);
        if (p == NBLK_ - 1) {
            g_done = 0u;
            __threadfence();
            g_pass = 0u;
        }
    }

    // ---- streaming pass (unchanged from best kernel) ---------------------
    const size_t idx4 = (size_t)blockIdx.x * 256 + tid;
    const float4* xb  = x + ((size_t)b * CIN_) * HW4_ + idx4;

    float4 a0 = make_float4(0.f, 0.f, 0.f, 0.f);
    float4 a1 = a0, a2 = a0;

    #pragma unroll 4
    for (int i = 0; i < CIN_; i++) {
        float4 v = __ldcs(&xb[(size_t)i * HW4_]);
        float4 c = sc[i];
        a0.x += v.x * c.x; a0.y += v.y * c.x; a0.z += v.z * c.x; a0.w += v.w * c.x;
        a1.x += v.x * c.y; a1.y += v.y * c.y; a1.z += v.z * c.y; a1.w += v.w * c.y;
        a2.x += v.x * c.z; a2.y += v.y * c.z; a2.z += v.z * c.z; a2.w += v.w * c.z;
    }

    const float b0 = bias[0], b1 = bias[1], b2 = bias[2];
    a0.x += b0; a0.y += b0; a0.z += b0; a0.w += b0;
    a1.x += b1; a1.y += b1; a1.z += b1; a1.w += b1;
    a2.x += b2; a2.y += b2; a2.z += b2; a2.w += b2;

    float4* ob = out + ((size_t)b * COUT_) * HW4_ + idx4;
    __stcg(&ob[0 * HW4_], a0);
    __stcg(&ob[1 * HW4_], a1);
    __stcg(&ob[2 * HW4_], a2);
}

// ---------------------------------------------------------------------------
// Launch. Input order (metadata): x, w, weight, bias, affine_w, affine_b
// ---------------------------------------------------------------------------
extern "C" void kernel_launch(void* const* d_in, const int* in_sizes, int n_in,
                              void* d_out, int out_size)
{
    const float* x        = (const float*)d_in[0];
    const float* w        = (const float*)d_in[1];
    const float* weight   = (const float*)d_in[2];
    const float* bias     = (const float*)d_in[3];
    const float* affine_w = (const float*)d_in[4];
    const float* affine_b = (const float*)d_in[5];
    float* out = (float*)d_out;

    dim3 grid(HW4_ / 256, B_);   // 64 x 16 = 1024 CTAs, single resident wave
    fused_torgb_kernel<<<grid, 256>>>(
        (const float4*)x, (const float4*)w, weight, bias,
        (const float4*)affine_w, affine_b, (float4*)out);
}

// round 8
// speedup vs baseline: 1.0379x; 1.0379x over previous
#include <cuda_runtime.h>
#include <cuda_bf16.h>

// Problem: ToRGBLayer  (B=16, CIN=128, COUT=3, WDIM=512, H=W=256)
// out[b,o,h,w] = sum_i x[b,i,h,w] * style[b,i] * weight[o,i] + bias[o]
// style[b,i]   = dot(w[b,:], affine_w[i,:]) + affine_b[i]
//
// R8: revert R7 fusion (grid barrier idled 768 consumer CTAs, DRAM 84->78%).
// Back to R6 structure: style kernel + PDL torgb (best, 84.1us). One delta:
// torgb uses 512-thread blocks (4 CTA/SM) so each channel-iteration touches
// an 8KB contiguous chunk instead of 4KB -> tests DRAM row-locality headroom.
// Warps/SM, regs (32), per-thread code unchanged.

#define B_    16
#define CIN_  128
#define COUT_ 3
#define WDIM_ 512
#define HW_   65536            // 256*256
#define HW4_  16384            // HW/4 float4 positions

// Scratch: coeff[b][i] = {style*w0, style*w1, style*w2, 0}
__device__ float4 g_coeff[B_ * CIN_];

// ---------------------------------------------------------------------------
// Kernel 1: coeff. One warp per (b,i). 2048 warps = 256 blocks x 256 threads.
// ---------------------------------------------------------------------------
__global__ void __launch_bounds__(256) style_kernel(
    const float4* __restrict__ w,         // [B, WDIM/4]
    const float*  __restrict__ weight,    // [COUT, CIN] (1x1 conv squeezed)
    const float4* __restrict__ affine_w,  // [CIN, WDIM/4]
    const float*  __restrict__ affine_b)  // [CIN]
{
    const int lane = threadIdx.x & 31;
    const int gw   = (blockIdx.x << 3) + (threadIdx.x >> 5);  // global warp id
    const int b    = gw >> 7;          // / CIN_
    const int i    = gw & (CIN_ - 1);

    const float4* wb = w + b * (WDIM_ / 4);
    const float4* aw = affine_w + i * (WDIM_ / 4);

    float acc = 0.f;
    #pragma unroll
    for (int k = 0; k < 4; k++) {
        float4 a = wb[lane + 32 * k];
        float4 c = aw[lane + 32 * k];
        acc += a.x * c.x + a.y * c.y + a.z * c.z + a.w * c.w;
    }
    #pragma unroll
    for (int off = 16; off > 0; off >>= 1)
        acc += __shfl_down_sync(0xffffffffu, acc, off);

    if (lane == 0) {
        float style = acc + affine_b[i];
        float4 c;
        c.x = style * weight[0 * CIN_ + i];
        c.y = style * weight[1 * CIN_ + i];
        c.z = style * weight[2 * CIN_ + i];
        c.w = 0.f;
        g_coeff[b * CIN_ + i] = c;
    }

    cudaTriggerProgrammaticLaunchCompletion();
}

// ---------------------------------------------------------------------------
// Kernel 2: streaming pass. grid = (HW4_/512, B) = (32,16), 512 threads,
// 4 CTA/SM. Per channel-iteration each CTA reads one 8KB contiguous chunk.
// Per-thread loop identical to the proven 32-reg version.
// ---------------------------------------------------------------------------
__global__ void __launch_bounds__(512, 4) torgb_kernel(
    const float4* __restrict__ x,     // [B, CIN, HW4_] as float4
    const float*  __restrict__ bias,  // [COUT]
    float4*       __restrict__ out)   // [B, COUT, HW4_] as float4
{
    __shared__ float4 sc[CIN_];

    const int tid = threadIdx.x;
    const int b   = blockIdx.y;

    const size_t idx4 = (size_t)blockIdx.x * 512 + tid;
    const float4* xb  = x + ((size_t)b * CIN_) * HW4_ + idx4;

    cudaGridDependencySynchronize();

    if (tid < CIN_) sc[tid] = g_coeff[b * CIN_ + tid];
    __syncthreads();

    float4 a0 = make_float4(0.f, 0.f, 0.f, 0.f);
    float4 a1 = a0, a2 = a0;

    #pragma unroll 4
    for (int i = 0; i < CIN_; i++) {
        float4 v = __ldcs(&xb[(size_t)i * HW4_]);
        float4 c = sc[i];
        a0.x += v.x * c.x; a0.y += v.y * c.x; a0.z += v.z * c.x; a0.w += v.w * c.x;
        a1.x += v.x * c.y; a1.y += v.y * c.y; a1.z += v.z * c.y; a1.w += v.w * c.y;
        a2.x += v.x * c.z; a2.y += v.y * c.z; a2.z += v.z * c.z; a2.w += v.w * c.z;
    }

    const float b0 = bias[0], b1 = bias[1], b2 = bias[2];
    a0.x += b0; a0.y += b0; a0.z += b0; a0.w += b0;
    a1.x += b1; a1.y += b1; a1.z += b1; a1.w += b1;
    a2.x += b2; a2.y += b2; a2.z += b2; a2.w += b2;

    float4* ob = out + ((size_t)b * COUT_) * HW4_ + idx4;
    __stcg(&ob[0 * HW4_], a0);
    __stcg(&ob[1 * HW4_], a1);
    __stcg(&ob[2 * HW4_], a2);
}

// ---------------------------------------------------------------------------
// Launch. Input order (metadata): x, w, weight, bias, affine_w, affine_b
// ---------------------------------------------------------------------------
extern "C" void kernel_launch(void* const* d_in, const int* in_sizes, int n_in,
                              void* d_out, int out_size)
{
    const float*  x        = (const float*)d_in[0];
    const float*  w        = (const float*)d_in[1];
    const float*  weight   = (const float*)d_in[2];
    const float*  bias     = (const float*)d_in[3];
    const float*  affine_w = (const float*)d_in[4];
    const float*  affine_b = (const float*)d_in[5];
    float* out = (float*)d_out;

    style_kernel<<<(B_ * CIN_) / 8, 256>>>((const float4*)w, weight,
                                           (const float4*)affine_w, affine_b);

    cudaLaunchConfig_t cfg = {};
    cfg.gridDim  = dim3(HW4_ / 512, B_);
    cfg.blockDim = dim3(512);
    cfg.dynamicSmemBytes = 0;
    cfg.stream = 0;

    cudaLaunchAttribute attrs[1];
    attrs[0].id = cudaLaunchAttributeProgrammaticStreamSerialization;
    attrs[0].val.programmaticStreamSerializationAllowed = 1;
    cfg.attrs = attrs;
    cfg.numAttrs = 1;

    cudaLaunchKernelEx(&cfg, torgb_kernel, (const float4*)x, bias, (float4*)out);
}